// round 12
// baseline (speedup 1.0000x reference)
#include <cuda_runtime.h>
#include <cuda_fp16.h>
#include <math.h>
#include <stdint.h>

#define DIMW 128
#define NG   100000
#define AS_B 272              // bytes per fp16 row (128*2 + 16 pad)

// ---------------- scratch (no allocs) ----------------
__device__ float g_pool[(size_t)NG * DIMW];
__device__ float g_cnt[NG];
__device__ int   g_is64;
__device__ __half g_WTh[3 * 128 * 128];   // W{1,2,3}^T fp16  [n][k]

// ---------------- kAtom smem layout (bytes) ----------------
#define SM_GID   0             // int[128] = 512
#define SM_B1    512           // float[128] = 512
#define SM_W     1024          // W fp16: 34816 -> ends 35840
#define SM_A     35840         // Ah 34816 ; sT (66048) reuses region -> ends 105472
#define SMEM_ATOM 105472

// ---------------- fused kGraph smem layout ----------------
#define GF_C     0             // cnt 512
#define GF_V     512           // W4 512
#define GF_B2    1024          // b2 512
#define GF_B3    1536          // b3 512
#define GF_P     2048          // partials 1024
#define GF_W2    3072          // 34816 -> 37888
#define GF_W3    37888         // 34816 -> 72704
#define GF_A     72704         // Ah 34816 -> 107520
#define SMEM_GF  107520

__device__ __forceinline__ uint32_t smem_u32(const void* p) {
    uint32_t a;
    asm("{ .reg .u64 t; cvta.to.shared.u64 t, %1; cvt.u32.u64 %0, t; }" : "=r"(a) : "l"(p));
    return a;
}
__device__ __forceinline__ void ldsm4(uint32_t& r0, uint32_t& r1, uint32_t& r2, uint32_t& r3,
                                      uint32_t addr) {
    asm volatile("ldmatrix.sync.aligned.m8n8.x4.shared.b16 {%0,%1,%2,%3}, [%4];"
                 : "=r"(r0), "=r"(r1), "=r"(r2), "=r"(r3) : "r"(addr));
}
__device__ __forceinline__ void mma16816(float* c, const uint32_t* a, uint32_t b0, uint32_t b1) {
    asm volatile("mma.sync.aligned.m16n8k16.row.col.f32.f16.f16.f32 "
                 "{%0,%1,%2,%3}, {%4,%5,%6,%7}, {%8,%9}, {%0,%1,%2,%3};"
                 : "+f"(c[0]), "+f"(c[1]), "+f"(c[2]), "+f"(c[3])
                 : "r"(a[0]), "r"(a[1]), "r"(a[2]), "r"(a[3]), "r"(b0), "r"(b1));
}

// ---------------------------------------------------------------------------
// 1-pass fp16 warp-tile core: 16 rows x 64 cols per warp, 16 warps = 128x128
// ---------------------------------------------------------------------------
__device__ __forceinline__ void mma_1pass(uint32_t A, uint32_t W, float acc[4][8]) {
    const int t = threadIdx.x, w = t >> 5, lane = t & 31;
    const int wm = w >> 1, wn = w & 1;
    const int lm = lane & 7, q = lane >> 3;
    const uint32_t aOff = (uint32_t)((wm * 16 + lm + (q & 1) * 8) * AS_B + ((q >> 1) * 8) * 2);
    const uint32_t bOff = (uint32_t)((wn * 64 + lm + (q >> 1) * 8) * AS_B + ((q & 1) * 8) * 2);
    const uint32_t Ah = A + aOff, Bb = W + bOff;
    #pragma unroll
    for (int kk = 0; kk < 8; kk++) {
        uint32_t ah[4], b[4][4];
        ldsm4(ah[0], ah[1], ah[2], ah[3], Ah + kk * 32);
        #pragma unroll
        for (int nb = 0; nb < 4; nb++)
            ldsm4(b[nb][0], b[nb][1], b[nb][2], b[nb][3], Bb + nb * 16 * AS_B + kk * 32);
        #pragma unroll
        for (int nb = 0; nb < 4; nb++) {
            mma16816(acc[nb],     ah, b[nb][0], b[nb][1]);
            mma16816(acc[nb] + 4, ah, b[nb][2], b[nb][3]);
        }
    }
}

// stage one prepped fp16 weight matrix into padded smem (NT threads)
template <int NT>
__device__ __forceinline__ void stage_W(char* sm, uint32_t wOff, int widx, int t) {
    for (int i = t; i < 256; i += NT) {
        const int r = i >> 1, h = i & 1;
        const uint4* ws = (const uint4*)(g_WTh + widx * 16384 + r * 128 + h * 64);
        char* d = sm + wOff + r * AS_B + h * 128;
        #pragma unroll
        for (int j = 0; j < 8; j++) ((uint4*)d)[j] = ws[j];
    }
}

// fp16 round-only store at (row m, float4-col c)
__device__ __forceinline__ void round_store(float4 x, char* dstH, int m, int c) {
    __half2 hp0 = __halves2half2(__float2half_rn(x.x), __float2half_rn(x.y));
    __half2 hp1 = __halves2half2(__float2half_rn(x.z), __float2half_rn(x.w));
    *(uint2*)(dstH + m * AS_B + c * 8) = make_uint2(*(uint32_t*)&hp0, *(uint32_t*)&hp1);
}

// ---------------------------------------------------------------------------
// kInit: zero pool+cnt, detect batch dtype, prep fp16 weights
// ---------------------------------------------------------------------------
__global__ void kInit(const int* __restrict__ batch32, int n,
                      const float* __restrict__ W1, const float* __restrict__ W2,
                      const float* __restrict__ W3) {
    size_t i = (size_t)blockIdx.x * blockDim.x + threadIdx.x;
    const size_t pool4 = (size_t)NG * DIMW / 4;
    if (i < pool4)
        ((float4*)g_pool)[i] = make_float4(0.f, 0.f, 0.f, 0.f);
    else if (i < pool4 + NG)
        g_cnt[i - pool4] = 0.0f;
    if (i < 3 * 16384) {
        int widx = (int)(i >> 14), e = (int)(i & 16383);
        int nn = e >> 7, kk = e & 127;
        const float* W = (widx == 0) ? W1 : (widx == 1) ? W2 : W3;
        g_WTh[i] = __float2half_rn(W[kk * 128 + nn]);
    }
    if (i == 0) g_is64 = (batch32[n - 1] == 0) ? 1 : 0;
}

// ---------------------------------------------------------------------------
// kAtomTC: persistent, 512 threads, 2 CTAs/SM, 1-pass fp16 core.
// Next-tile LDGs issued before the reduce so their latency hides under it.
// ---------------------------------------------------------------------------
__global__ void __launch_bounds__(512, 2) kAtomTC(
    const float* __restrict__ feat, const void* __restrict__ batch, int n,
    const float* __restrict__ b1, float* __restrict__ outFeat, int ntiles)
{
    extern __shared__ char sm[];
    const uint32_t smb = smem_u32(sm);
    const int t = threadIdx.x, lane = t & 31, w = t >> 5;
    const int wm = w >> 1, wn = w & 1;
    const int is64 = g_is64;
    const int mb = t >> 5, c = t & 31;

    const int per = (ntiles + gridDim.x - 1) / gridDim.x;
    const int t0 = blockIdx.x * per;
    const int t1 = min(t0 + per, ntiles);
    if (t0 >= t1) return;

    if (t < 128) ((float*)(sm + SM_B1))[t] = b1[t];
    stage_W<512>(sm, SM_W, 0, t);

    // prologue: convert tile t0
    #pragma unroll
    for (int j = 0; j < 8; j++) {
        const int m = mb + j * 16;
        long long row = (long long)t0 * 128 + m;
        float4 x = make_float4(0.f, 0.f, 0.f, 0.f);
        if (row < n) {
            x = __ldcs(((const float4*)(feat + (size_t)row * 128)) + c);
            __stcs(((float4*)(outFeat + (size_t)row * 128)) + c, x);
        }
        round_store(x, sm + SM_A, m, c);
    }
    if (t < 128) {
        long long row = (long long)t0 * 128 + t;
        int g = -1;
        if (row < n)
            g = is64 ? (int)((const long long*)batch)[row] : ((const int*)batch)[row];
        ((int*)(sm + SM_GID))[t] = g;
    }

    for (int i = t0; i < t1; ++i) {
        __syncthreads();   // Ah(i) + gid(i) visible

        // 1) mma (1-pass)
        float acc[4][8];
        #pragma unroll
        for (int a = 0; a < 4; a++)
            #pragma unroll
            for (int b = 0; b < 8; b++) acc[a][b] = 0.0f;
        mma_1pass(smb + SM_A, smb + SM_W, acc);
        __syncthreads();   // all warps done reading Ah

        // 2) epilogue: bias + silu -> transposed sT (stride 129) in A region
        float* sT = (float*)(sm + SM_A);
        const float* sB1 = (const float*)(sm + SM_B1);
        #pragma unroll
        for (int nb = 0; nb < 4; nb++) {
            #pragma unroll
            for (int g = 0; g < 2; g++) {
                const int n0 = wn * 64 + nb * 16 + g * 8 + (lane & 3) * 2;
                const int r0 = wm * 16 + (lane >> 2);
                #pragma unroll
                for (int j = 0; j < 4; j++) {
                    const int nn = n0 + (j & 1);
                    const int mm = r0 + (j >> 1) * 8;
                    float x = acc[nb][g * 4 + j] + sB1[nn];
                    sT[nn * 129 + mm] = x / (1.0f + __expf(-x));
                }
            }
        }
        __syncthreads();   // sT visible

        // 3) issue next-tile LDGs (latency hides under the reduce below)
        const bool more = (i + 1 < t1);
        float4 x[8];
        int gnext = -1;
        if (more) {
            #pragma unroll
            for (int j = 0; j < 8; j++) {
                const int m = mb + j * 16;
                long long row = (long long)(i + 1) * 128 + m;
                x[j] = make_float4(0.f, 0.f, 0.f, 0.f);
                if (row < n) {
                    x[j] = __ldcs(((const float4*)(feat + (size_t)row * 128)) + c);
                    __stcs(((float4*)(outFeat + (size_t)row * 128)) + c, x[j]);
                }
            }
            if (t < 128) {
                long long row = (long long)(i + 1) * 128 + t;
                if (row < n)
                    gnext = is64 ? (int)((const long long*)batch)[row]
                                 : ((const int*)batch)[row];
            }
        }

        // 4) run-length segment reduce (batch sorted); 4 quarters of 32 atoms
        const int d = t & 127, hh = t >> 7;
        const int mS = hh * 32, mE = mS + 32;
        const int* gid = (const int*)(sm + SM_GID);
        float run = 0.0f;
        int len = 0, cur = gid[mS];
        for (int mm = mS; mm < mE; ++mm) {
            int g = gid[mm];
            if (g != cur) {
                if (cur >= 0) {
                    atomicAdd(&g_pool[(size_t)cur * 128 + d], run);
                    if (d == 0) atomicAdd(&g_cnt[cur], (float)len);
                }
                run = 0.0f; len = 0; cur = g;
            }
            if (g >= 0) { run += sT[d * 129 + mm]; len++; }
        }
        if (cur >= 0) {
            atomicAdd(&g_pool[(size_t)cur * 128 + d], run);
            if (d == 0) atomicAdd(&g_cnt[cur], (float)len);
        }
        __syncthreads();   // all done reading sT / gid

        // 5) store next tile into Ah + gid
        if (more) {
            #pragma unroll
            for (int j = 0; j < 8; j++)
                round_store(x[j], sm + SM_A, mb + j * 16, c);
            if (t < 128) ((int*)(sm + SM_GID))[t] = gnext;
        }
    }
}

// ---------------------------------------------------------------------------
// kGraphF: fused graph head, 1-pass both GEMMs, no g_pool2 round-trip.
//   h2 = pooled @ W2 + cnt*b2   (re-rounded to fp16 in smem)
//   out = silu(h2 @ W3 + b3) @ W4 + b4
// ---------------------------------------------------------------------------
__global__ void __launch_bounds__(512, 2) kGraphF(
    const float* __restrict__ b2, const float* __restrict__ b3,
    const float* __restrict__ W4, const float* __restrict__ b4,
    float* __restrict__ outS)
{
    extern __shared__ char sm[];
    const uint32_t smb = smem_u32(sm);
    const int t = threadIdx.x, lane = t & 31, w = t >> 5;
    const int wm = w >> 1, wn = w & 1;
    const int a0 = blockIdx.x * 128;
    const int mb = t >> 5, c = t & 31;

    float* sCnt = (float*)(sm + GF_C);
    float* sV   = (float*)(sm + GF_V);
    float* sB2  = (float*)(sm + GF_B2);
    float* sB3  = (float*)(sm + GF_B3);
    float* sP   = (float*)(sm + GF_P);
    if (t < 128) {
        sCnt[t] = (a0 + t < NG) ? g_cnt[a0 + t] : 0.0f;
        sV[t]  = W4[t];
        sB2[t] = b2[t];
        sB3[t] = b3[t];
    }
    stage_W<512>(sm, GF_W2, 1, t);
    stage_W<512>(sm, GF_W3, 2, t);
    // load pooled tile -> fp16 Ah
    #pragma unroll
    for (int j = 0; j < 8; j++) {
        const int m = mb + j * 16;
        int row = a0 + m;
        float4 x = (row < NG) ? ((const float4*)(g_pool + (size_t)row * 128))[c]
                              : make_float4(0.f, 0.f, 0.f, 0.f);
        round_store(x, sm + GF_A, m, c);
    }
    __syncthreads();

    // GEMM2: pooled @ W2
    float acc[4][8];
    #pragma unroll
    for (int a = 0; a < 4; a++)
        #pragma unroll
        for (int b = 0; b < 8; b++) acc[a][b] = 0.0f;
    mma_1pass(smb + GF_A, smb + GF_W2, acc);
    __syncthreads();   // done reading Ah

    // epilogue: h2 = acc + cnt*b2 -> fp16 back into Ah
    {
        char* Ah = sm + GF_A;
        #pragma unroll
        for (int nb = 0; nb < 4; nb++) {
            #pragma unroll
            for (int g = 0; g < 2; g++) {
                const int n0 = wn * 64 + nb * 16 + g * 8 + (lane & 3) * 2;
                const int r0 = wm * 16 + (lane >> 2);
                #pragma unroll
                for (int rr = 0; rr < 2; rr++) {
                    const int m = r0 + rr * 8;
                    float cn = sCnt[m];
                    float v0 = acc[nb][g * 4 + rr * 2 + 0] + cn * sB2[n0];
                    float v1 = acc[nb][g * 4 + rr * 2 + 1] + cn * sB2[n0 + 1];
                    __half2 hv = __halves2half2(__float2half_rn(v0), __float2half_rn(v1));
                    *(uint32_t*)(Ah + m * AS_B + n0 * 2) = *(uint32_t*)&hv;
                }
            }
        }
    }
    __syncthreads();   // h2 visible

    // GEMM3: h2 @ W3
    #pragma unroll
    for (int a = 0; a < 4; a++)
        #pragma unroll
        for (int b = 0; b < 8; b++) acc[a][b] = 0.0f;
    mma_1pass(smb + GF_A, smb + GF_W3, acc);

    // head: +b3, silu, x W4, reduce over dims
    float s0 = 0.0f, s1 = 0.0f;
    #pragma unroll
    for (int nb = 0; nb < 4; nb++) {
        #pragma unroll
        for (int g = 0; g < 2; g++) {
            const int n0 = wn * 64 + nb * 16 + g * 8 + (lane & 3) * 2;
            #pragma unroll
            for (int j = 0; j < 4; j++) {
                const int nn = n0 + (j & 1);
                float x = acc[nb][g * 4 + j] + sB3[nn];
                float h = x / (1.0f + __expf(-x));
                float p = h * sV[nn];
                if (j < 2) s0 += p; else s1 += p;
            }
        }
    }
    s0 += __shfl_xor_sync(0xFFFFFFFF, s0, 1);
    s0 += __shfl_xor_sync(0xFFFFFFFF, s0, 2);
    s1 += __shfl_xor_sync(0xFFFFFFFF, s1, 1);
    s1 += __shfl_xor_sync(0xFFFFFFFF, s1, 2);
    if ((lane & 3) == 0) {
        const int mr = wm * 16 + (lane >> 2);
        sP[wn * 128 + mr] = s0;
        sP[wn * 128 + mr + 8] = s1;
    }
    __syncthreads();
    if (t < 128) {
        int row = a0 + t;
        if (row < NG) outS[row] = sP[t] + sP[128 + t] + b4[0];
    }
}

// ---------------------------------------------------------------------------
extern "C" void kernel_launch(void* const* d_in, const int* in_sizes, int n_in,
                              void* d_out, int out_size)
{
    const float* feat  = (const float*)d_in[0];
    const void*  batch = d_in[1];
    const float* W1 = (const float*)d_in[2];
    const float* b1 = (const float*)d_in[3];
    const float* W2 = (const float*)d_in[4];
    const float* b2 = (const float*)d_in[5];
    const float* W3 = (const float*)d_in[6];
    const float* b3 = (const float*)d_in[7];
    const float* W4 = (const float*)d_in[8];
    const float* b4 = (const float*)d_in[9];

    const int n = in_sizes[0] / DIMW;
    float* outS    = (float*)d_out;
    float* outFeat = (float*)d_out + NG;

    cudaFuncSetAttribute(kAtomTC, cudaFuncAttributeMaxDynamicSharedMemorySize, SMEM_ATOM);
    cudaFuncSetAttribute(kGraphF, cudaFuncAttributeMaxDynamicSharedMemorySize, SMEM_GF);

    {
        size_t total = (size_t)NG * DIMW / 4 + NG;
        kInit<<<(int)((total + 255) / 256), 256>>>((const int*)batch, n, W1, W2, W3);
    }
    {
        int ntiles = (n + 127) / 128;
        kAtomTC<<<296, 512, SMEM_ATOM>>>(feat, batch, n, b1, outFeat, ntiles);
    }
    {
        int grid = (NG + 127) / 128;
        kGraphF<<<grid, 512, SMEM_GF>>>(b2, b3, W4, b4, outS);
    }
}

// round 13
// speedup vs baseline: 1.1083x; 1.1083x over previous
#include <cuda_runtime.h>
#include <cuda_fp16.h>
#include <math.h>
#include <stdint.h>

#define DIMW 128
#define NG   100000
#define AS_B 272              // bytes per fp16 row (128*2 + 16 pad)

// ---------------- scratch (no allocs) ----------------
__device__ float g_pool[(size_t)NG * DIMW];
__device__ float g_cnt[NG];
__device__ int   g_is64;
__device__ __half g_WTh[3 * 128 * 128];   // W{1,2,3}^T fp16  [n][k]

// ---------------- kAtom smem layout (bytes) ----------------
#define SM_GID   0             // int[128] = 512
#define SM_B1    512           // float[128] = 512
#define SM_W     1024          // W fp16: 34816 -> ends 35840
#define SM_A     35840         // Ah 34816 ; sT (66048) reuses region -> ends 105472
#define SMEM_ATOM 105472

// ---------------- fused kGraph smem layout ----------------
#define GF_C     0             // cnt 512
#define GF_V     512           // W4 512
#define GF_B2    1024          // b2 512
#define GF_B3    1536          // b3 512
#define GF_P     2048          // partials 1024
#define GF_W2    3072          // 34816 -> 37888
#define GF_W3    37888         // 34816 -> 72704
#define GF_A     72704         // Ah 34816 -> 107520
#define SMEM_GF  107520

__device__ __forceinline__ uint32_t smem_u32(const void* p) {
    uint32_t a;
    asm("{ .reg .u64 t; cvta.to.shared.u64 t, %1; cvt.u32.u64 %0, t; }" : "=r"(a) : "l"(p));
    return a;
}
__device__ __forceinline__ void ldsm4(uint32_t& r0, uint32_t& r1, uint32_t& r2, uint32_t& r3,
                                      uint32_t addr) {
    asm volatile("ldmatrix.sync.aligned.m8n8.x4.shared.b16 {%0,%1,%2,%3}, [%4];"
                 : "=r"(r0), "=r"(r1), "=r"(r2), "=r"(r3) : "r"(addr));
}
__device__ __forceinline__ void mma16816(float* c, const uint32_t* a, uint32_t b0, uint32_t b1) {
    asm volatile("mma.sync.aligned.m16n8k16.row.col.f32.f16.f16.f32 "
                 "{%0,%1,%2,%3}, {%4,%5,%6,%7}, {%8,%9}, {%0,%1,%2,%3};"
                 : "+f"(c[0]), "+f"(c[1]), "+f"(c[2]), "+f"(c[3])
                 : "r"(a[0]), "r"(a[1]), "r"(a[2]), "r"(a[3]), "r"(b0), "r"(b1));
}

// ---------------------------------------------------------------------------
// 1-pass fp16 warp-tile core: 16 rows x 64 cols per warp, 16 warps = 128x128
// ---------------------------------------------------------------------------
__device__ __forceinline__ void mma_1pass(uint32_t A, uint32_t W, float acc[4][8]) {
    const int t = threadIdx.x, w = t >> 5, lane = t & 31;
    const int wm = w >> 1, wn = w & 1;
    const int lm = lane & 7, q = lane >> 3;
    const uint32_t aOff = (uint32_t)((wm * 16 + lm + (q & 1) * 8) * AS_B + ((q >> 1) * 8) * 2);
    const uint32_t bOff = (uint32_t)((wn * 64 + lm + (q >> 1) * 8) * AS_B + ((q & 1) * 8) * 2);
    const uint32_t Ah = A + aOff, Bb = W + bOff;
    #pragma unroll
    for (int kk = 0; kk < 8; kk++) {
        uint32_t ah[4], b[4][4];
        ldsm4(ah[0], ah[1], ah[2], ah[3], Ah + kk * 32);
        #pragma unroll
        for (int nb = 0; nb < 4; nb++)
            ldsm4(b[nb][0], b[nb][1], b[nb][2], b[nb][3], Bb + nb * 16 * AS_B + kk * 32);
        #pragma unroll
        for (int nb = 0; nb < 4; nb++) {
            mma16816(acc[nb],     ah, b[nb][0], b[nb][1]);
            mma16816(acc[nb] + 4, ah, b[nb][2], b[nb][3]);
        }
    }
}

// stage one prepped fp16 weight matrix into padded smem (NT threads)
template <int NT>
__device__ __forceinline__ void stage_W(char* sm, uint32_t wOff, int widx, int t) {
    for (int i = t; i < 256; i += NT) {
        const int r = i >> 1, h = i & 1;
        const uint4* ws = (const uint4*)(g_WTh + widx * 16384 + r * 128 + h * 64);
        char* d = sm + wOff + r * AS_B + h * 128;
        #pragma unroll
        for (int j = 0; j < 8; j++) ((uint4*)d)[j] = ws[j];
    }
}

// fp16 round-only store at (row m, float4-col c)
__device__ __forceinline__ void round_store(float4 x, char* dstH, int m, int c) {
    __half2 hp0 = __halves2half2(__float2half_rn(x.x), __float2half_rn(x.y));
    __half2 hp1 = __halves2half2(__float2half_rn(x.z), __float2half_rn(x.w));
    *(uint2*)(dstH + m * AS_B + c * 8) = make_uint2(*(uint32_t*)&hp0, *(uint32_t*)&hp1);
}

// ---------------------------------------------------------------------------
// kInit: zero pool+cnt, detect batch dtype, prep fp16 weights
// ---------------------------------------------------------------------------
__global__ void kInit(const int* __restrict__ batch32, int n,
                      const float* __restrict__ W1, const float* __restrict__ W2,
                      const float* __restrict__ W3) {
    size_t i = (size_t)blockIdx.x * blockDim.x + threadIdx.x;
    const size_t pool4 = (size_t)NG * DIMW / 4;
    if (i < pool4)
        ((float4*)g_pool)[i] = make_float4(0.f, 0.f, 0.f, 0.f);
    else if (i < pool4 + NG)
        g_cnt[i - pool4] = 0.0f;
    if (i < 3 * 16384) {
        int widx = (int)(i >> 14), e = (int)(i & 16383);
        int nn = e >> 7, kk = e & 127;
        const float* W = (widx == 0) ? W1 : (widx == 1) ? W2 : W3;
        g_WTh[i] = __float2half_rn(W[kk * 128 + nn]);
    }
    if (i == 0) g_is64 = (batch32[n - 1] == 0) ? 1 : 0;
}

// ---------------------------------------------------------------------------
// kAtomTC: persistent, 512 threads, 2 CTAs/SM, 1-pass fp16 core (R11 form:
// convert at loop top so load registers die immediately into STS — no spills).
// ---------------------------------------------------------------------------
__global__ void __launch_bounds__(512, 2) kAtomTC(
    const float* __restrict__ feat, const void* __restrict__ batch, int n,
    const float* __restrict__ b1, float* __restrict__ outFeat, int ntiles)
{
    extern __shared__ char sm[];
    const uint32_t smb = smem_u32(sm);
    const int t = threadIdx.x, lane = t & 31, w = t >> 5;
    const int wm = w >> 1, wn = w & 1;
    const int is64 = g_is64;
    const int mb = t >> 5, c = t & 31;

    const int per = (ntiles + gridDim.x - 1) / gridDim.x;
    const int t0 = blockIdx.x * per;
    const int t1 = min(t0 + per, ntiles);
    if (t0 >= t1) return;

    if (t < 128) ((float*)(sm + SM_B1))[t] = b1[t];
    stage_W<512>(sm, SM_W, 0, t);
    __syncthreads();

    for (int i = t0; i < t1; ++i) {
        // 1) convert: streaming LDG -> fp16 round -> STS ; passthrough STG ; gids
        #pragma unroll
        for (int j = 0; j < 8; j++) {
            const int m = mb + j * 16;
            long long row = (long long)i * 128 + m;
            float4 x = make_float4(0.f, 0.f, 0.f, 0.f);
            if (row < n) {
                x = __ldcs(((const float4*)(feat + (size_t)row * 128)) + c);
                __stcs(((float4*)(outFeat + (size_t)row * 128)) + c, x);
            }
            round_store(x, sm + SM_A, m, c);
        }
        if (t < 128) {
            long long row = (long long)i * 128 + t;
            int g = -1;
            if (row < n)
                g = is64 ? (int)((const long long*)batch)[row] : ((const int*)batch)[row];
            ((int*)(sm + SM_GID))[t] = g;
        }
        __syncthreads();

        // 2) mma (1-pass)
        float acc[4][8];
        #pragma unroll
        for (int a = 0; a < 4; a++)
            #pragma unroll
            for (int b = 0; b < 8; b++) acc[a][b] = 0.0f;
        mma_1pass(smb + SM_A, smb + SM_W, acc);
        __syncthreads();   // all warps done reading Ah

        // 3) epilogue: bias + silu -> transposed sT (stride 129) in A region
        float* sT = (float*)(sm + SM_A);
        const float* sB1 = (const float*)(sm + SM_B1);
        #pragma unroll
        for (int nb = 0; nb < 4; nb++) {
            #pragma unroll
            for (int g = 0; g < 2; g++) {
                const int n0 = wn * 64 + nb * 16 + g * 8 + (lane & 3) * 2;
                const int r0 = wm * 16 + (lane >> 2);
                #pragma unroll
                for (int j = 0; j < 4; j++) {
                    const int nn = n0 + (j & 1);
                    const int mm = r0 + (j >> 1) * 8;
                    float x = acc[nb][g * 4 + j] + sB1[nn];
                    sT[nn * 129 + mm] = x / (1.0f + __expf(-x));
                }
            }
        }
        __syncthreads();

        // 4) run-length segment reduce (batch sorted); 4 quarters of 32 atoms
        const int d = t & 127, hh = t >> 7;
        const int mS = hh * 32, mE = mS + 32;
        const int* gid = (const int*)(sm + SM_GID);
        float run = 0.0f;
        int len = 0, cur = gid[mS];
        for (int mm = mS; mm < mE; ++mm) {
            int g = gid[mm];
            if (g != cur) {
                if (cur >= 0) {
                    atomicAdd(&g_pool[(size_t)cur * 128 + d], run);
                    if (d == 0) atomicAdd(&g_cnt[cur], (float)len);
                }
                run = 0.0f; len = 0; cur = g;
            }
            if (g >= 0) { run += sT[d * 129 + mm]; len++; }
        }
        if (cur >= 0) {
            atomicAdd(&g_pool[(size_t)cur * 128 + d], run);
            if (d == 0) atomicAdd(&g_cnt[cur], (float)len);
        }
        __syncthreads();   // reduce done before next convert overwrites sT/A
    }
}

// ---------------------------------------------------------------------------
// kGraphF: fused graph head, 1-pass both GEMMs, no intermediate round-trip.
//   h2 = pooled @ W2 + cnt*b2   (re-rounded to fp16 in smem)
//   out = silu(h2 @ W3 + b3) @ W4 + b4
// ---------------------------------------------------------------------------
__global__ void __launch_bounds__(512, 2) kGraphF(
    const float* __restrict__ b2, const float* __restrict__ b3,
    const float* __restrict__ W4, const float* __restrict__ b4,
    float* __restrict__ outS)
{
    extern __shared__ char sm[];
    const uint32_t smb = smem_u32(sm);
    const int t = threadIdx.x, lane = t & 31, w = t >> 5;
    const int wm = w >> 1, wn = w & 1;
    const int a0 = blockIdx.x * 128;
    const int mb = t >> 5, c = t & 31;

    float* sCnt = (float*)(sm + GF_C);
    float* sV   = (float*)(sm + GF_V);
    float* sB2  = (float*)(sm + GF_B2);
    float* sB3  = (float*)(sm + GF_B3);
    float* sP   = (float*)(sm + GF_P);
    if (t < 128) {
        sCnt[t] = (a0 + t < NG) ? g_cnt[a0 + t] : 0.0f;
        sV[t]  = W4[t];
        sB2[t] = b2[t];
        sB3[t] = b3[t];
    }
    stage_W<512>(sm, GF_W2, 1, t);
    stage_W<512>(sm, GF_W3, 2, t);
    // load pooled tile -> fp16 Ah
    #pragma unroll
    for (int j = 0; j < 8; j++) {
        const int m = mb + j * 16;
        int row = a0 + m;
        float4 x = (row < NG) ? ((const float4*)(g_pool + (size_t)row * 128))[c]
                              : make_float4(0.f, 0.f, 0.f, 0.f);
        round_store(x, sm + GF_A, m, c);
    }
    __syncthreads();

    // GEMM2: pooled @ W2
    float acc[4][8];
    #pragma unroll
    for (int a = 0; a < 4; a++)
        #pragma unroll
        for (int b = 0; b < 8; b++) acc[a][b] = 0.0f;
    mma_1pass(smb + GF_A, smb + GF_W2, acc);
    __syncthreads();   // done reading Ah

    // epilogue: h2 = acc + cnt*b2 -> fp16 back into Ah
    {
        char* Ah = sm + GF_A;
        #pragma unroll
        for (int nb = 0; nb < 4; nb++) {
            #pragma unroll
            for (int g = 0; g < 2; g++) {
                const int n0 = wn * 64 + nb * 16 + g * 8 + (lane & 3) * 2;
                const int r0 = wm * 16 + (lane >> 2);
                #pragma unroll
                for (int rr = 0; rr < 2; rr++) {
                    const int m = r0 + rr * 8;
                    float cn = sCnt[m];
                    float v0 = acc[nb][g * 4 + rr * 2 + 0] + cn * sB2[n0];
                    float v1 = acc[nb][g * 4 + rr * 2 + 1] + cn * sB2[n0 + 1];
                    __half2 hv = __halves2half2(__float2half_rn(v0), __float2half_rn(v1));
                    *(uint32_t*)(Ah + m * AS_B + n0 * 2) = *(uint32_t*)&hv;
                }
            }
        }
    }
    __syncthreads();   // h2 visible

    // GEMM3: h2 @ W3
    #pragma unroll
    for (int a = 0; a < 4; a++)
        #pragma unroll
        for (int b = 0; b < 8; b++) acc[a][b] = 0.0f;
    mma_1pass(smb + GF_A, smb + GF_W3, acc);

    // head: +b3, silu, x W4, reduce over dims
    float s0 = 0.0f, s1 = 0.0f;
    #pragma unroll
    for (int nb = 0; nb < 4; nb++) {
        #pragma unroll
        for (int g = 0; g < 2; g++) {
            const int n0 = wn * 64 + nb * 16 + g * 8 + (lane & 3) * 2;
            #pragma unroll
            for (int j = 0; j < 4; j++) {
                const int nn = n0 + (j & 1);
                float x = acc[nb][g * 4 + j] + sB3[nn];
                float h = x / (1.0f + __expf(-x));
                float p = h * sV[nn];
                if (j < 2) s0 += p; else s1 += p;
            }
        }
    }
    s0 += __shfl_xor_sync(0xFFFFFFFF, s0, 1);
    s0 += __shfl_xor_sync(0xFFFFFFFF, s0, 2);
    s1 += __shfl_xor_sync(0xFFFFFFFF, s1, 1);
    s1 += __shfl_xor_sync(0xFFFFFFFF, s1, 2);
    if ((lane & 3) == 0) {
        const int mr = wm * 16 + (lane >> 2);
        sP[wn * 128 + mr] = s0;
        sP[wn * 128 + mr + 8] = s1;
    }
    __syncthreads();
    if (t < 128) {
        int row = a0 + t;
        if (row < NG) outS[row] = sP[t] + sP[128 + t] + b4[0];
    }
}

// ---------------------------------------------------------------------------
extern "C" void kernel_launch(void* const* d_in, const int* in_sizes, int n_in,
                              void* d_out, int out_size)
{
    const float* feat  = (const float*)d_in[0];
    const void*  batch = d_in[1];
    const float* W1 = (const float*)d_in[2];
    const float* b1 = (const float*)d_in[3];
    const float* W2 = (const float*)d_in[4];
    const float* b2 = (const float*)d_in[5];
    const float* W3 = (const float*)d_in[6];
    const float* b3 = (const float*)d_in[7];
    const float* W4 = (const float*)d_in[8];
    const float* b4 = (const float*)d_in[9];

    const int n = in_sizes[0] / DIMW;
    float* outS    = (float*)d_out;
    float* outFeat = (float*)d_out + NG;

    cudaFuncSetAttribute(kAtomTC, cudaFuncAttributeMaxDynamicSharedMemorySize, SMEM_ATOM);
    cudaFuncSetAttribute(kGraphF, cudaFuncAttributeMaxDynamicSharedMemorySize, SMEM_GF);

    {
        size_t total = (size_t)NG * DIMW / 4 + NG;
        kInit<<<(int)((total + 255) / 256), 256>>>((const int*)batch, n, W1, W2, W3);
    }
    {
        int ntiles = (n + 127) / 128;
        kAtomTC<<<296, 512, SMEM_ATOM>>>(feat, batch, n, b1, outFeat, ntiles);
    }
    {
        int grid = (NG + 127) / 128;
        kGraphF<<<grid, 512, SMEM_GF>>>(b2, b3, W4, b4, outS);
    }
}

// round 14
// speedup vs baseline: 1.2571x; 1.1343x over previous
#include <cuda_runtime.h>
#include <cuda_fp16.h>
#include <math.h>
#include <stdint.h>

#define DIMW 128
#define NG   100000
#define AS_B 272              // bytes per fp16 row (128*2 + 16 pad)

// ---------------- scratch (no allocs) ----------------
__device__ float g_pool[(size_t)NG * DIMW];
__device__ float g_cnt[NG];
__device__ int   g_is64;
__device__ __half g_WTh[3 * 128 * 128];   // W{1,2,3}^T fp16  [n][k]

// ---------------- kAtom smem layout (bytes) ----------------
#define SM_GID   0             // int[2][128] = 1024
#define SM_B1    1024          // float[128] = 512
#define SM_W     1536          // W fp16: 34816 -> ends 36352
#define SM_A     36352         // Ah 34816 -> ends 71168
#define SM_ST    71168         // sT fp16 128x130 = 33280 -> ends 104448
#define SMEM_ATOM 104448

// ---------------- fused kGraph smem layout ----------------
#define GF_C     0             // cnt 512
#define GF_V     512           // W4 512
#define GF_B2    1024          // b2 512
#define GF_B3    1536          // b3 512
#define GF_P     2048          // partials 1024
#define GF_W2    3072          // 34816 -> 37888
#define GF_W3    37888         // 34816 -> 72704
#define GF_A     72704         // Ah 34816 -> 107520
#define SMEM_GF  107520

__device__ __forceinline__ uint32_t smem_u32(const void* p) {
    uint32_t a;
    asm("{ .reg .u64 t; cvta.to.shared.u64 t, %1; cvt.u32.u64 %0, t; }" : "=r"(a) : "l"(p));
    return a;
}
__device__ __forceinline__ void ldsm4(uint32_t& r0, uint32_t& r1, uint32_t& r2, uint32_t& r3,
                                      uint32_t addr) {
    asm volatile("ldmatrix.sync.aligned.m8n8.x4.shared.b16 {%0,%1,%2,%3}, [%4];"
                 : "=r"(r0), "=r"(r1), "=r"(r2), "=r"(r3) : "r"(addr));
}
__device__ __forceinline__ void mma16816(float* c, const uint32_t* a, uint32_t b0, uint32_t b1) {
    asm volatile("mma.sync.aligned.m16n8k16.row.col.f32.f16.f16.f32 "
                 "{%0,%1,%2,%3}, {%4,%5,%6,%7}, {%8,%9}, {%0,%1,%2,%3};"
                 : "+f"(c[0]), "+f"(c[1]), "+f"(c[2]), "+f"(c[3])
                 : "r"(a[0]), "r"(a[1]), "r"(a[2]), "r"(a[3]), "r"(b0), "r"(b1));
}

// ---------------------------------------------------------------------------
// 1-pass fp16 warp-tile core: 16 rows x 64 cols per warp, 16 warps = 128x128
// ---------------------------------------------------------------------------
__device__ __forceinline__ void mma_1pass(uint32_t A, uint32_t W, float acc[4][8]) {
    const int t = threadIdx.x, w = t >> 5, lane = t & 31;
    const int wm = w >> 1, wn = w & 1;
    const int lm = lane & 7, q = lane >> 3;
    const uint32_t aOff = (uint32_t)((wm * 16 + lm + (q & 1) * 8) * AS_B + ((q >> 1) * 8) * 2);
    const uint32_t bOff = (uint32_t)((wn * 64 + lm + (q >> 1) * 8) * AS_B + ((q & 1) * 8) * 2);
    const uint32_t Ah = A + aOff, Bb = W + bOff;
    #pragma unroll
    for (int kk = 0; kk < 8; kk++) {
        uint32_t ah[4], b[4][4];
        ldsm4(ah[0], ah[1], ah[2], ah[3], Ah + kk * 32);
        #pragma unroll
        for (int nb = 0; nb < 4; nb++)
            ldsm4(b[nb][0], b[nb][1], b[nb][2], b[nb][3], Bb + nb * 16 * AS_B + kk * 32);
        #pragma unroll
        for (int nb = 0; nb < 4; nb++) {
            mma16816(acc[nb],     ah, b[nb][0], b[nb][1]);
            mma16816(acc[nb] + 4, ah, b[nb][2], b[nb][3]);
        }
    }
}

// stage one prepped fp16 weight matrix into padded smem (NT threads)
template <int NT>
__device__ __forceinline__ void stage_W(char* sm, uint32_t wOff, int widx, int t) {
    for (int i = t; i < 256; i += NT) {
        const int r = i >> 1, h = i & 1;
        const uint4* ws = (const uint4*)(g_WTh + widx * 16384 + r * 128 + h * 64);
        char* d = sm + wOff + r * AS_B + h * 128;
        #pragma unroll
        for (int j = 0; j < 8; j++) ((uint4*)d)[j] = ws[j];
    }
}

// fp16 round-only store at (row m, float4-col c)
__device__ __forceinline__ void round_store(float4 x, char* dstH, int m, int c) {
    __half2 hp0 = __halves2half2(__float2half_rn(x.x), __float2half_rn(x.y));
    __half2 hp1 = __halves2half2(__float2half_rn(x.z), __float2half_rn(x.w));
    *(uint2*)(dstH + m * AS_B + c * 8) = make_uint2(*(uint32_t*)&hp0, *(uint32_t*)&hp1);
}

// ---------------------------------------------------------------------------
// kInit: zero pool+cnt, detect batch dtype, prep fp16 weights
// ---------------------------------------------------------------------------
__global__ void kInit(const int* __restrict__ batch32, int n,
                      const float* __restrict__ W1, const float* __restrict__ W2,
                      const float* __restrict__ W3) {
    size_t i = (size_t)blockIdx.x * blockDim.x + threadIdx.x;
    const size_t pool4 = (size_t)NG * DIMW / 4;
    if (i < pool4)
        ((float4*)g_pool)[i] = make_float4(0.f, 0.f, 0.f, 0.f);
    else if (i < pool4 + NG)
        g_cnt[i - pool4] = 0.0f;
    if (i < 3 * 16384) {
        int widx = (int)(i >> 14), e = (int)(i & 16383);
        int nn = e >> 7, kk = e & 127;
        const float* W = (widx == 0) ? W1 : (widx == 1) ? W2 : W3;
        g_WTh[i] = __float2half_rn(W[kk * 128 + nn]);
    }
    if (i == 0) g_is64 = (batch32[n - 1] == 0) ? 1 : 0;
}

// ---------------------------------------------------------------------------
// kAtomTC: persistent, 512 threads, 2 CTAs/SM, 1-pass fp16 core.
// sT is a SEPARATE fp16 buffer -> only 2 barriers per tile:
//   sync / mma+epilogue / sync / convert(i+1)+reduce(i)
// ---------------------------------------------------------------------------
__global__ void __launch_bounds__(512, 2) kAtomTC(
    const float* __restrict__ feat, const void* __restrict__ batch, int n,
    const float* __restrict__ b1, float* __restrict__ outFeat, int ntiles)
{
    extern __shared__ char sm[];
    const uint32_t smb = smem_u32(sm);
    const int t = threadIdx.x, lane = t & 31, w = t >> 5;
    const int wm = w >> 1, wn = w & 1;
    const int is64 = g_is64;
    const int mb = t >> 5, c = t & 31;

    const int per = (ntiles + gridDim.x - 1) / gridDim.x;
    const int t0 = blockIdx.x * per;
    const int t1 = min(t0 + per, ntiles);
    if (t0 >= t1) return;

    if (t < 128) ((float*)(sm + SM_B1))[t] = b1[t];
    stage_W<512>(sm, SM_W, 0, t);

    // prologue: convert tile t0 into Ah + gid slot (t0&1)
    #pragma unroll
    for (int j = 0; j < 8; j++) {
        const int m = mb + j * 16;
        long long row = (long long)t0 * 128 + m;
        float4 x = make_float4(0.f, 0.f, 0.f, 0.f);
        if (row < n) {
            x = __ldcs(((const float4*)(feat + (size_t)row * 128)) + c);
            __stcs(((float4*)(outFeat + (size_t)row * 128)) + c, x);
        }
        round_store(x, sm + SM_A, m, c);
    }
    if (t < 128) {
        long long row = (long long)t0 * 128 + t;
        int g = -1;
        if (row < n)
            g = is64 ? (int)((const long long*)batch)[row] : ((const int*)batch)[row];
        ((int*)(sm + SM_GID))[(t0 & 1) * 128 + t] = g;
    }

    for (int i = t0; i < t1; ++i) {
        __syncthreads();   // Ah(i)+gid(i) visible; sT16(i-1) fully reduced

        // 1) mma (1-pass) + epilogue into disjoint sT16
        float acc[4][8];
        #pragma unroll
        for (int a = 0; a < 4; a++)
            #pragma unroll
            for (int b = 0; b < 8; b++) acc[a][b] = 0.0f;
        mma_1pass(smb + SM_A, smb + SM_W, acc);

        {
            char* sT = sm + SM_ST;
            const float* sB1 = (const float*)(sm + SM_B1);
            #pragma unroll
            for (int nb = 0; nb < 4; nb++) {
                #pragma unroll
                for (int g = 0; g < 2; g++) {
                    const int n0 = wn * 64 + nb * 16 + g * 8 + (lane & 3) * 2;
                    const int r0 = wm * 16 + (lane >> 2);
                    #pragma unroll
                    for (int j = 0; j < 4; j++) {
                        const int nn = n0 + (j & 1);
                        const int mm = r0 + (j >> 1) * 8;
                        float x = acc[nb][g * 4 + j] + sB1[nn];
                        float s = x * __fdividef(1.0f, 1.0f + __expf(-x));
                        *(__half*)(sT + nn * 260 + mm * 2) = __float2half_rn(s);
                    }
                }
            }
        }
        __syncthreads();   // sT16(i) visible; Ah free (all mma done)

        // 2) convert(i+1) into Ah + gid slot ((i+1)&1)
        const bool more = (i + 1 < t1);
        if (more) {
            #pragma unroll
            for (int j = 0; j < 8; j++) {
                const int m = mb + j * 16;
                long long row = (long long)(i + 1) * 128 + m;
                float4 x = make_float4(0.f, 0.f, 0.f, 0.f);
                if (row < n) {
                    x = __ldcs(((const float4*)(feat + (size_t)row * 128)) + c);
                    __stcs(((float4*)(outFeat + (size_t)row * 128)) + c, x);
                }
                round_store(x, sm + SM_A, m, c);
            }
            if (t < 128) {
                long long row = (long long)(i + 1) * 128 + t;
                int g = -1;
                if (row < n)
                    g = is64 ? (int)((const long long*)batch)[row] : ((const int*)batch)[row];
                ((int*)(sm + SM_GID))[((i + 1) & 1) * 128 + t] = g;
            }
        }

        // 3) run-length segment reduce of sT16(i); half2 = 2 atoms per load
        const int d = t & 127, hh = t >> 7;
        const int mS = hh * 32;
        const int* gid = (const int*)(sm + SM_GID) + (i & 1) * 128;
        const char* sT = sm + SM_ST;
        float run = 0.0f;
        int len = 0, cur = gid[mS];
        #pragma unroll 4
        for (int it = 0; it < 16; ++it) {
            const int mm = mS + it * 2;
            __half2 hv = *(const __half2*)(sT + d * 260 + mm * 2);
            float2 fv = __half22float2(hv);
            int g0 = gid[mm];
            if (g0 != cur) {
                if (cur >= 0) {
                    atomicAdd(&g_pool[(size_t)cur * 128 + d], run);
                    if (d == 0) atomicAdd(&g_cnt[cur], (float)len);
                }
                run = 0.0f; len = 0; cur = g0;
            }
            if (g0 >= 0) { run += fv.x; len++; }
            int g1 = gid[mm + 1];
            if (g1 != cur) {
                if (cur >= 0) {
                    atomicAdd(&g_pool[(size_t)cur * 128 + d], run);
                    if (d == 0) atomicAdd(&g_cnt[cur], (float)len);
                }
                run = 0.0f; len = 0; cur = g1;
            }
            if (g1 >= 0) { run += fv.y; len++; }
        }
        if (cur >= 0) {
            atomicAdd(&g_pool[(size_t)cur * 128 + d], run);
            if (d == 0) atomicAdd(&g_cnt[cur], (float)len);
        }
    }
}

// ---------------------------------------------------------------------------
// kGraphF: fused graph head, 1-pass both GEMMs, no intermediate round-trip.
// ---------------------------------------------------------------------------
__global__ void __launch_bounds__(512, 2) kGraphF(
    const float* __restrict__ b2, const float* __restrict__ b3,
    const float* __restrict__ W4, const float* __restrict__ b4,
    float* __restrict__ outS)
{
    extern __shared__ char sm[];
    const uint32_t smb = smem_u32(sm);
    const int t = threadIdx.x, lane = t & 31, w = t >> 5;
    const int wm = w >> 1, wn = w & 1;
    const int a0 = blockIdx.x * 128;
    const int mb = t >> 5, c = t & 31;

    float* sCnt = (float*)(sm + GF_C);
    float* sV   = (float*)(sm + GF_V);
    float* sB2  = (float*)(sm + GF_B2);
    float* sB3  = (float*)(sm + GF_B3);
    float* sP   = (float*)(sm + GF_P);
    if (t < 128) {
        sCnt[t] = (a0 + t < NG) ? g_cnt[a0 + t] : 0.0f;
        sV[t]  = W4[t];
        sB2[t] = b2[t];
        sB3[t] = b3[t];
    }
    stage_W<512>(sm, GF_W2, 1, t);
    stage_W<512>(sm, GF_W3, 2, t);
    #pragma unroll
    for (int j = 0; j < 8; j++) {
        const int m = mb + j * 16;
        int row = a0 + m;
        float4 x = (row < NG) ? ((const float4*)(g_pool + (size_t)row * 128))[c]
                              : make_float4(0.f, 0.f, 0.f, 0.f);
        round_store(x, sm + GF_A, m, c);
    }
    __syncthreads();

    // GEMM2: pooled @ W2
    float acc[4][8];
    #pragma unroll
    for (int a = 0; a < 4; a++)
        #pragma unroll
        for (int b = 0; b < 8; b++) acc[a][b] = 0.0f;
    mma_1pass(smb + GF_A, smb + GF_W2, acc);
    __syncthreads();   // done reading Ah

    // epilogue: h2 = acc + cnt*b2 -> fp16 back into Ah
    {
        char* Ah = sm + GF_A;
        #pragma unroll
        for (int nb = 0; nb < 4; nb++) {
            #pragma unroll
            for (int g = 0; g < 2; g++) {
                const int n0 = wn * 64 + nb * 16 + g * 8 + (lane & 3) * 2;
                const int r0 = wm * 16 + (lane >> 2);
                #pragma unroll
                for (int rr = 0; rr < 2; rr++) {
                    const int m = r0 + rr * 8;
                    float cn = sCnt[m];
                    float v0 = acc[nb][g * 4 + rr * 2 + 0] + cn * sB2[n0];
                    float v1 = acc[nb][g * 4 + rr * 2 + 1] + cn * sB2[n0 + 1];
                    __half2 hv = __halves2half2(__float2half_rn(v0), __float2half_rn(v1));
                    *(uint32_t*)(Ah + m * AS_B + n0 * 2) = *(uint32_t*)&hv;
                }
            }
        }
    }
    __syncthreads();   // h2 visible

    // GEMM3: h2 @ W3
    #pragma unroll
    for (int a = 0; a < 4; a++)
        #pragma unroll
        for (int b = 0; b < 8; b++) acc[a][b] = 0.0f;
    mma_1pass(smb + GF_A, smb + GF_W3, acc);

    // head: +b3, silu, x W4, reduce over dims
    float s0 = 0.0f, s1 = 0.0f;
    #pragma unroll
    for (int nb = 0; nb < 4; nb++) {
        #pragma unroll
        for (int g = 0; g < 2; g++) {
            const int n0 = wn * 64 + nb * 16 + g * 8 + (lane & 3) * 2;
            #pragma unroll
            for (int j = 0; j < 4; j++) {
                const int nn = n0 + (j & 1);
                float x = acc[nb][g * 4 + j] + sB3[nn];
                float h = x * __fdividef(1.0f, 1.0f + __expf(-x));
                float p = h * sV[nn];
                if (j < 2) s0 += p; else s1 += p;
            }
        }
    }
    s0 += __shfl_xor_sync(0xFFFFFFFF, s0, 1);
    s0 += __shfl_xor_sync(0xFFFFFFFF, s0, 2);
    s1 += __shfl_xor_sync(0xFFFFFFFF, s1, 1);
    s1 += __shfl_xor_sync(0xFFFFFFFF, s1, 2);
    if ((lane & 3) == 0) {
        const int mr = wm * 16 + (lane >> 2);
        sP[wn * 128 + mr] = s0;
        sP[wn * 128 + mr + 8] = s1;
    }
    __syncthreads();
    if (t < 128) {
        int row = a0 + t;
        if (row < NG) outS[row] = sP[t] + sP[128 + t] + b4[0];
    }
}

// ---------------------------------------------------------------------------
extern "C" void kernel_launch(void* const* d_in, const int* in_sizes, int n_in,
                              void* d_out, int out_size)
{
    const float* feat  = (const float*)d_in[0];
    const void*  batch = d_in[1];
    const float* W1 = (const float*)d_in[2];
    const float* b1 = (const float*)d_in[3];
    const float* W2 = (const float*)d_in[4];
    const float* b2 = (const float*)d_in[5];
    const float* W3 = (const float*)d_in[6];
    const float* b3 = (const float*)d_in[7];
    const float* W4 = (const float*)d_in[8];
    const float* b4 = (const float*)d_in[9];

    const int n = in_sizes[0] / DIMW;
    float* outS    = (float*)d_out;
    float* outFeat = (float*)d_out + NG;

    cudaFuncSetAttribute(kAtomTC, cudaFuncAttributeMaxDynamicSharedMemorySize, SMEM_ATOM);
    cudaFuncSetAttribute(kGraphF, cudaFuncAttributeMaxDynamicSharedMemorySize, SMEM_GF);

    {
        size_t total = (size_t)NG * DIMW / 4 + NG;
        kInit<<<(int)((total + 255) / 256), 256>>>((const int*)batch, n, W1, W2, W3);
    }
    {
        int ntiles = (n + 127) / 128;
        kAtomTC<<<296, 512, SMEM_ATOM>>>(feat, batch, n, b1, outFeat, ntiles);
    }
    {
        int grid = (NG + 127) / 128;
        kGraphF<<<grid, 512, SMEM_GF>>>(b2, b3, W4, b4, outS);
    }
}

// round 15
// speedup vs baseline: 1.3484x; 1.0726x over previous
#include <cuda_runtime.h>
#include <cuda_fp16.h>
#include <math.h>
#include <stdint.h>

#define DIMW 128
#define NG   100000
#define AS_B 272              // bytes per fp16 row (128*2 + 16 pad)

// ---------------- scratch (no allocs) ----------------
__device__ float g_pool[(size_t)NG * DIMW];
__device__ float g_cnt[NG];
__device__ int   g_is64;
__device__ int   g_ticket;
__device__ __half g_WTh[3 * 128 * 128];   // W{1,2,3}^T fp16  [n][k]

// ---------------- kAtom smem layout (bytes) ----------------
#define SM_GID   0             // int[2][128] = 1024
#define SM_B1    1024          // float[128] = 512
#define SM_TK    1536          // int ticket broadcast
#define SM_W     1664          // W fp16: 34816 -> ends 36480
#define SM_A     36480         // Ah 34816 -> ends 71296
#define SM_ST    71296         // sT fp16 128x130 = 33280 -> ends 104576
#define SMEM_ATOM 104576

// ---------------- fused kGraph smem layout ----------------
#define GF_C     0             // cnt 512
#define GF_V     512           // W4 512
#define GF_B2    1024          // b2 512
#define GF_B3    1536          // b3 512
#define GF_P     2048          // partials 1024
#define GF_W2    3072          // 34816 -> 37888
#define GF_W3    37888         // 34816 -> 72704
#define GF_A     72704         // Ah 34816 -> 107520
#define SMEM_GF  107520

__device__ __forceinline__ uint32_t smem_u32(const void* p) {
    uint32_t a;
    asm("{ .reg .u64 t; cvta.to.shared.u64 t, %1; cvt.u32.u64 %0, t; }" : "=r"(a) : "l"(p));
    return a;
}
__device__ __forceinline__ void ldsm4(uint32_t& r0, uint32_t& r1, uint32_t& r2, uint32_t& r3,
                                      uint32_t addr) {
    asm volatile("ldmatrix.sync.aligned.m8n8.x4.shared.b16 {%0,%1,%2,%3}, [%4];"
                 : "=r"(r0), "=r"(r1), "=r"(r2), "=r"(r3) : "r"(addr));
}
__device__ __forceinline__ void mma16816(float* c, const uint32_t* a, uint32_t b0, uint32_t b1) {
    asm volatile("mma.sync.aligned.m16n8k16.row.col.f32.f16.f16.f32 "
                 "{%0,%1,%2,%3}, {%4,%5,%6,%7}, {%8,%9}, {%0,%1,%2,%3};"
                 : "+f"(c[0]), "+f"(c[1]), "+f"(c[2]), "+f"(c[3])
                 : "r"(a[0]), "r"(a[1]), "r"(a[2]), "r"(a[3]), "r"(b0), "r"(b1));
}

// ---------------------------------------------------------------------------
// 1-pass fp16 warp-tile core: 16 rows x 64 cols per warp, 16 warps = 128x128
// ---------------------------------------------------------------------------
__device__ __forceinline__ void mma_1pass(uint32_t A, uint32_t W, float acc[4][8]) {
    const int t = threadIdx.x, w = t >> 5, lane = t & 31;
    const int wm = w >> 1, wn = w & 1;
    const int lm = lane & 7, q = lane >> 3;
    const uint32_t aOff = (uint32_t)((wm * 16 + lm + (q & 1) * 8) * AS_B + ((q >> 1) * 8) * 2);
    const uint32_t bOff = (uint32_t)((wn * 64 + lm + (q >> 1) * 8) * AS_B + ((q & 1) * 8) * 2);
    const uint32_t Ah = A + aOff, Bb = W + bOff;
    #pragma unroll
    for (int kk = 0; kk < 8; kk++) {
        uint32_t ah[4], b[4][4];
        ldsm4(ah[0], ah[1], ah[2], ah[3], Ah + kk * 32);
        #pragma unroll
        for (int nb = 0; nb < 4; nb++)
            ldsm4(b[nb][0], b[nb][1], b[nb][2], b[nb][3], Bb + nb * 16 * AS_B + kk * 32);
        #pragma unroll
        for (int nb = 0; nb < 4; nb++) {
            mma16816(acc[nb],     ah, b[nb][0], b[nb][1]);
            mma16816(acc[nb] + 4, ah, b[nb][2], b[nb][3]);
        }
    }
}

// stage one prepped fp16 weight matrix into padded smem (NT threads)
template <int NT>
__device__ __forceinline__ void stage_W(char* sm, uint32_t wOff, int widx, int t) {
    for (int i = t; i < 256; i += NT) {
        const int r = i >> 1, h = i & 1;
        const uint4* ws = (const uint4*)(g_WTh + widx * 16384 + r * 128 + h * 64);
        char* d = sm + wOff + r * AS_B + h * 128;
        #pragma unroll
        for (int j = 0; j < 8; j++) ((uint4*)d)[j] = ws[j];
    }
}

// fp16 round-only store at (row m, float4-col c)
__device__ __forceinline__ void round_store(float4 x, char* dstH, int m, int c) {
    __half2 hp0 = __halves2half2(__float2half_rn(x.x), __float2half_rn(x.y));
    __half2 hp1 = __halves2half2(__float2half_rn(x.z), __float2half_rn(x.w));
    *(uint2*)(dstH + m * AS_B + c * 8) = make_uint2(*(uint32_t*)&hp0, *(uint32_t*)&hp1);
}

// ---------------------------------------------------------------------------
// kInit: zero pool+cnt+ticket, detect batch dtype, prep fp16 weights
// ---------------------------------------------------------------------------
__global__ void kInit(const int* __restrict__ batch32, int n,
                      const float* __restrict__ W1, const float* __restrict__ W2,
                      const float* __restrict__ W3) {
    size_t i = (size_t)blockIdx.x * blockDim.x + threadIdx.x;
    const size_t pool4 = (size_t)NG * DIMW / 4;
    if (i < pool4)
        ((float4*)g_pool)[i] = make_float4(0.f, 0.f, 0.f, 0.f);
    else if (i < pool4 + NG)
        g_cnt[i - pool4] = 0.0f;
    if (i < 3 * 16384) {
        int widx = (int)(i >> 14), e = (int)(i & 16383);
        int nn = e >> 7, kk = e & 127;
        const float* W = (widx == 0) ? W1 : (widx == 1) ? W2 : W3;
        g_WTh[i] = __float2half_rn(W[kk * 128 + nn]);
    }
    if (i == 0) {
        g_is64 = (batch32[n - 1] == 0) ? 1 : 0;
        g_ticket = 0;
    }
}

// ---------------------------------------------------------------------------
// convert tile i -> Ah + passthrough + gid slot p  (MLP-4 batched)
// ---------------------------------------------------------------------------
__device__ __forceinline__ void convert_tile(
    const float* __restrict__ feat, float* __restrict__ outFeat,
    const void* __restrict__ batch, int is64, long long n,
    long long tile, char* sm, int p, int t)
{
    const int mb = t >> 5, c = t & 31;
    #pragma unroll
    for (int b = 0; b < 2; b++) {
        float4 x[4];
        #pragma unroll
        for (int jj = 0; jj < 4; jj++) {
            const int m = mb + (b * 4 + jj) * 16;
            long long row = tile * 128 + m;
            x[jj] = (row < n) ? __ldcs(((const float4*)(feat + (size_t)row * 128)) + c)
                              : make_float4(0.f, 0.f, 0.f, 0.f);
        }
        #pragma unroll
        for (int jj = 0; jj < 4; jj++) {
            const int m = mb + (b * 4 + jj) * 16;
            long long row = tile * 128 + m;
            if (row < n)
                __stcs(((float4*)(outFeat + (size_t)row * 128)) + c, x[jj]);
            round_store(x[jj], sm + SM_A, m, c);
        }
    }
    if (t < 128) {
        long long row = tile * 128 + t;
        int g = -1;
        if (row < n)
            g = is64 ? (int)((const long long*)batch)[row] : ((const int*)batch)[row];
        ((int*)(sm + SM_GID))[p * 128 + t] = g;
    }
}

// ---------------------------------------------------------------------------
// kAtomTC: persistent, 512 threads, 2 CTAs/SM, dynamic tile ticketing.
// Phases: [sync] mma+epi(i) + grab ticket [sync] convert(next)+reduce(i)
// ---------------------------------------------------------------------------
__global__ void __launch_bounds__(512, 2) kAtomTC(
    const float* __restrict__ feat, const void* __restrict__ batch, int n,
    const float* __restrict__ b1, float* __restrict__ outFeat, int ntiles)
{
    extern __shared__ char sm[];
    const uint32_t smb = smem_u32(sm);
    const int t = threadIdx.x, lane = t & 31, w = t >> 5;
    const int wm = w >> 1, wn = w & 1;
    const int is64 = g_is64;

    if (t < 128) ((float*)(sm + SM_B1))[t] = b1[t];
    stage_W<512>(sm, SM_W, 0, t);

    // prologue: grab first tile
    if (t == 0) *(int*)(sm + SM_TK) = atomicAdd(&g_ticket, 1);
    __syncthreads();
    int i = *(const int*)(sm + SM_TK);
    if (i >= ntiles) return;

    convert_tile(feat, outFeat, batch, is64, n, i, sm, 0, t);
    int p = 0;

    while (true) {
        __syncthreads();   // Ah(i)+gid(i) visible; sT(prev) fully reduced

        // 1) mma (1-pass) + grab next ticket + epilogue into disjoint sT16
        float acc[4][8];
        #pragma unroll
        for (int a = 0; a < 4; a++)
            #pragma unroll
            for (int b = 0; b < 8; b++) acc[a][b] = 0.0f;
        if (t == 0) *(int*)(sm + SM_TK) = atomicAdd(&g_ticket, 1);
        mma_1pass(smb + SM_A, smb + SM_W, acc);

        {
            char* sT = sm + SM_ST;
            const float* sB1 = (const float*)(sm + SM_B1);
            #pragma unroll
            for (int nb = 0; nb < 4; nb++) {
                #pragma unroll
                for (int g = 0; g < 2; g++) {
                    const int n0 = wn * 64 + nb * 16 + g * 8 + (lane & 3) * 2;
                    const int r0 = wm * 16 + (lane >> 2);
                    #pragma unroll
                    for (int j = 0; j < 4; j++) {
                        const int nn = n0 + (j & 1);
                        const int mm = r0 + (j >> 1) * 8;
                        float x = acc[nb][g * 4 + j] + sB1[nn];
                        float s = x * __fdividef(1.0f, 1.0f + __expf(-x));
                        *(__half*)(sT + nn * 260 + mm * 2) = __float2half_rn(s);
                    }
                }
            }
        }
        __syncthreads();   // sT16(i) + ticket visible; Ah free

        const int inext = *(const int*)(sm + SM_TK);
        const bool more = inext < ntiles;

        // 2) convert(inext) into Ah + gid slot p^1
        if (more)
            convert_tile(feat, outFeat, batch, is64, n, inext, sm, p ^ 1, t);

        // 3) run-length segment reduce of sT16(i); half2 = 2 atoms per load
        const int d = t & 127, hh = t >> 7;
        const int mS = hh * 32;
        const int* gid = (const int*)(sm + SM_GID) + p * 128;
        const char* sT = sm + SM_ST;
        float run = 0.0f;
        int len = 0, cur = gid[mS];
        #pragma unroll 4
        for (int it = 0; it < 16; ++it) {
            const int mm = mS + it * 2;
            __half2 hv = *(const __half2*)(sT + d * 260 + mm * 2);
            float2 fv = __half22float2(hv);
            int g0 = gid[mm];
            if (g0 != cur) {
                if (cur >= 0) {
                    atomicAdd(&g_pool[(size_t)cur * 128 + d], run);
                    if (d == 0) atomicAdd(&g_cnt[cur], (float)len);
                }
                run = 0.0f; len = 0; cur = g0;
            }
            if (g0 >= 0) { run += fv.x; len++; }
            int g1 = gid[mm + 1];
            if (g1 != cur) {
                if (cur >= 0) {
                    atomicAdd(&g_pool[(size_t)cur * 128 + d], run);
                    if (d == 0) atomicAdd(&g_cnt[cur], (float)len);
                }
                run = 0.0f; len = 0; cur = g1;
            }
            if (g1 >= 0) { run += fv.y; len++; }
        }
        if (cur >= 0) {
            atomicAdd(&g_pool[(size_t)cur * 128 + d], run);
            if (d == 0) atomicAdd(&g_cnt[cur], (float)len);
        }

        if (!more) break;
        i = inext;
        p ^= 1;
    }
}

// ---------------------------------------------------------------------------
// kGraphF: fused graph head, 1-pass both GEMMs, no intermediate round-trip.
// ---------------------------------------------------------------------------
__global__ void __launch_bounds__(512, 2) kGraphF(
    const float* __restrict__ b2, const float* __restrict__ b3,
    const float* __restrict__ W4, const float* __restrict__ b4,
    float* __restrict__ outS)
{
    extern __shared__ char sm[];
    const uint32_t smb = smem_u32(sm);
    const int t = threadIdx.x, lane = t & 31, w = t >> 5;
    const int wm = w >> 1, wn = w & 1;
    const int a0 = blockIdx.x * 128;
    const int mb = t >> 5, c = t & 31;

    float* sCnt = (float*)(sm + GF_C);
    float* sV   = (float*)(sm + GF_V);
    float* sB2  = (float*)(sm + GF_B2);
    float* sB3  = (float*)(sm + GF_B3);
    float* sP   = (float*)(sm + GF_P);
    if (t < 128) {
        sCnt[t] = (a0 + t < NG) ? g_cnt[a0 + t] : 0.0f;
        sV[t]  = W4[t];
        sB2[t] = b2[t];
        sB3[t] = b3[t];
    }
    stage_W<512>(sm, GF_W2, 1, t);
    stage_W<512>(sm, GF_W3, 2, t);
    #pragma unroll
    for (int j = 0; j < 8; j++) {
        const int m = mb + j * 16;
        int row = a0 + m;
        float4 x = (row < NG) ? ((const float4*)(g_pool + (size_t)row * 128))[c]
                              : make_float4(0.f, 0.f, 0.f, 0.f);
        round_store(x, sm + GF_A, m, c);
    }
    __syncthreads();

    // GEMM2: pooled @ W2
    float acc[4][8];
    #pragma unroll
    for (int a = 0; a < 4; a++)
        #pragma unroll
        for (int b = 0; b < 8; b++) acc[a][b] = 0.0f;
    mma_1pass(smb + GF_A, smb + GF_W2, acc);
    __syncthreads();   // done reading Ah

    // epilogue: h2 = acc + cnt*b2 -> fp16 back into Ah
    {
        char* Ah = sm + GF_A;
        #pragma unroll
        for (int nb = 0; nb < 4; nb++) {
            #pragma unroll
            for (int g = 0; g < 2; g++) {
                const int n0 = wn * 64 + nb * 16 + g * 8 + (lane & 3) * 2;
                const int r0 = wm * 16 + (lane >> 2);
                #pragma unroll
                for (int rr = 0; rr < 2; rr++) {
                    const int m = r0 + rr * 8;
                    float cn = sCnt[m];
                    float v0 = acc[nb][g * 4 + rr * 2 + 0] + cn * sB2[n0];
                    float v1 = acc[nb][g * 4 + rr * 2 + 1] + cn * sB2[n0 + 1];
                    __half2 hv = __halves2half2(__float2half_rn(v0), __float2half_rn(v1));
                    *(uint32_t*)(Ah + m * AS_B + n0 * 2) = *(uint32_t*)&hv;
                }
            }
        }
    }
    __syncthreads();   // h2 visible

    // GEMM3: h2 @ W3
    #pragma unroll
    for (int a = 0; a < 4; a++)
        #pragma unroll
        for (int b = 0; b < 8; b++) acc[a][b] = 0.0f;
    mma_1pass(smb + GF_A, smb + GF_W3, acc);

    // head: +b3, silu, x W4, reduce over dims
    float s0 = 0.0f, s1 = 0.0f;
    #pragma unroll
    for (int nb = 0; nb < 4; nb++) {
        #pragma unroll
        for (int g = 0; g < 2; g++) {
            const int n0 = wn * 64 + nb * 16 + g * 8 + (lane & 3) * 2;
            #pragma unroll
            for (int j = 0; j < 4; j++) {
                const int nn = n0 + (j & 1);
                float x = acc[nb][g * 4 + j] + sB3[nn];
                float h = x * __fdividef(1.0f, 1.0f + __expf(-x));
                float p = h * sV[nn];
                if (j < 2) s0 += p; else s1 += p;
            }
        }
    }
    s0 += __shfl_xor_sync(0xFFFFFFFF, s0, 1);
    s0 += __shfl_xor_sync(0xFFFFFFFF, s0, 2);
    s1 += __shfl_xor_sync(0xFFFFFFFF, s1, 1);
    s1 += __shfl_xor_sync(0xFFFFFFFF, s1, 2);
    if ((lane & 3) == 0) {
        const int mr = wm * 16 + (lane >> 2);
        sP[wn * 128 + mr] = s0;
        sP[wn * 128 + mr + 8] = s1;
    }
    __syncthreads();
    if (t < 128) {
        int row = a0 + t;
        if (row < NG) outS[row] = sP[t] + sP[128 + t] + b4[0];
    }
}

// ---------------------------------------------------------------------------
extern "C" void kernel_launch(void* const* d_in, const int* in_sizes, int n_in,
                              void* d_out, int out_size)
{
    const float* feat  = (const float*)d_in[0];
    const void*  batch = d_in[1];
    const float* W1 = (const float*)d_in[2];
    const float* b1 = (const float*)d_in[3];
    const float* W2 = (const float*)d_in[4];
    const float* b2 = (const float*)d_in[5];
    const float* W3 = (const float*)d_in[6];
    const float* b3 = (const float*)d_in[7];
    const float* W4 = (const float*)d_in[8];
    const float* b4 = (const float*)d_in[9];

    const int n = in_sizes[0] / DIMW;
    float* outS    = (float*)d_out;
    float* outFeat = (float*)d_out + NG;

    cudaFuncSetAttribute(kAtomTC, cudaFuncAttributeMaxDynamicSharedMemorySize, SMEM_ATOM);
    cudaFuncSetAttribute(kGraphF, cudaFuncAttributeMaxDynamicSharedMemorySize, SMEM_GF);

    {
        size_t total = (size_t)NG * DIMW / 4 + NG;
        kInit<<<(int)((total + 255) / 256), 256>>>((const int*)batch, n, W1, W2, W3);
    }
    {
        int ntiles = (n + 127) / 128;
        kAtomTC<<<296, 512, SMEM_ATOM>>>(feat, batch, n, b1, outFeat, ntiles);
    }
    {
        int grid = (NG + 127) / 128;
        kGraphF<<<grid, 512, SMEM_GF>>>(b2, b3, W4, b4, outS);
    }
}